// round 15
// baseline (speedup 1.0000x reference)
#include <cuda_runtime.h>
#include <cuda_fp16.h>
#include <cstdint>

constexpr int N = 8192;
constexpr int F = 256;

// ---------------- scratch ----------------
__device__ __align__(16) float  g_H [(size_t)N * F];
__device__ __align__(16) __half g_Hh[(size_t)N * F];
__device__ float g_sdst[N];

__device__ __forceinline__ uint32_t tf32r(float x) {
    uint32_t u; asm("cvt.rna.tf32.f32 %0, %1;" : "=r"(u) : "f"(x));
    return u;
}

// ---------------- Kernel 1: H = x@W + bias (tf32 mma, 2-stage) + fused sdst -
__global__ void __launch_bounds__(256, 2)
gemm_mma_kernel(const float* __restrict__ A, const float* __restrict__ B,
                const float* __restrict__ bias, const float* __restrict__ phi,
                float* __restrict__ C, __half* __restrict__ Ch,
                float* __restrict__ sdst)
{
    __shared__ uint32_t As[2][4][128][8];
    __shared__ uint32_t Bs[2][4][64][8];

    const int tid = threadIdx.x;
    const int lane = tid & 31, wid = tid >> 5;
    const int wm = wid & 3, wn = wid >> 2;
    const int row0 = blockIdx.y * 128, col0 = blockIdx.x * 64;

    float c[2][4][4];
#pragma unroll
    for (int mt = 0; mt < 2; ++mt)
#pragma unroll
        for (int nt = 0; nt < 4; ++nt)
#pragma unroll
            for (int e = 0; e < 4; ++e) c[mt][nt][e] = 0.f;

    int a_m[4], a_ks[4], a_q[4];
    const float* a_src[4];
#pragma unroll
    for (int i = 0; i < 4; ++i) {
        int idx = tid + i * 256;
        a_m[i] = idx >> 3; a_ks[i] = (idx >> 1) & 3; a_q[i] = idx & 1;
        a_src[i] = A + (size_t)(row0 + a_m[i]) * F + a_ks[i] * 8 + a_q[i] * 4;
    }
    int b_k[2], b_nb[2];
    const float* b_src[2];
#pragma unroll
    for (int i = 0; i < 2; ++i) {
        int idx = tid + i * 256;
        b_k[i] = idx >> 4; b_nb[i] = (idx & 15) * 4;
        b_src[i] = B + (size_t)b_k[i] * F + col0 + b_nb[i];
    }

    float4 ra[4], rb[2];
#pragma unroll
    for (int i = 0; i < 4; ++i) ra[i] = *reinterpret_cast<const float4*>(a_src[i]);
#pragma unroll
    for (int i = 0; i < 2; ++i) rb[i] = *reinterpret_cast<const float4*>(b_src[i]);

    auto store_stage = [&](int st) {
#pragma unroll
        for (int i = 0; i < 4; ++i) {
            uint32_t t[4] = {tf32r(ra[i].x), tf32r(ra[i].y), tf32r(ra[i].z), tf32r(ra[i].w)};
            int s = a_m[i] & 7;
            int qd = a_q[i] ^ (s >> 2), p = s & 3;
            uint32_t* dst = &As[st][a_ks[i]][a_m[i]][qd * 4];
            dst[0] = t[0 ^ p]; dst[1] = t[1 ^ p];
            dst[2] = t[2 ^ p]; dst[3] = t[3 ^ p];
        }
#pragma unroll
        for (int i = 0; i < 2; ++i) {
            uint32_t t[4] = {tf32r(rb[i].x), tf32r(rb[i].y), tf32r(rb[i].z), tf32r(rb[i].w)};
#pragma unroll
            for (int e = 0; e < 4; ++e) {
                int n = b_nb[i] + e;
                Bs[st][b_k[i] >> 3][n][(b_k[i] & 7) ^ (n & 7)] = t[e];
            }
        }
    };

    store_stage(0);
    __syncthreads();

#pragma unroll
    for (int kb = 0; kb < 8; ++kb) {
        const int st = kb & 1;
        if (kb < 7) {
#pragma unroll
            for (int i = 0; i < 4; ++i)
                ra[i] = *reinterpret_cast<const float4*>(a_src[i] + (kb + 1) * 32);
#pragma unroll
            for (int i = 0; i < 2; ++i)
                rb[i] = *reinterpret_cast<const float4*>(b_src[i] + (size_t)(kb + 1) * 32 * F);
        }
#pragma unroll
        for (int ks = 0; ks < 4; ++ks) {
            uint32_t a[2][4], b[4][2];
#pragma unroll
            for (int mt = 0; mt < 2; ++mt) {
                int r = wm * 32 + mt * 16 + (lane >> 2);
                int j0 = (lane & 3) ^ (r & 7);
                a[mt][0] = As[st][ks][r][j0];
                a[mt][1] = As[st][ks][r + 8][j0];
                a[mt][2] = As[st][ks][r][j0 ^ 4];
                a[mt][3] = As[st][ks][r + 8][j0 ^ 4];
            }
#pragma unroll
            for (int nt = 0; nt < 4; ++nt) {
                int n = wn * 32 + nt * 8 + (lane >> 2);
                int j0 = (lane & 3) ^ (n & 7);
                b[nt][0] = Bs[st][ks][n][j0];
                b[nt][1] = Bs[st][ks][n][j0 ^ 4];
            }
#pragma unroll
            for (int mt = 0; mt < 2; ++mt)
#pragma unroll
                for (int nt = 0; nt < 4; ++nt)
                    asm volatile(
                        "mma.sync.aligned.m16n8k8.row.col.f32.tf32.tf32.f32 "
                        "{%0,%1,%2,%3}, {%4,%5,%6,%7}, {%8,%9}, {%0,%1,%2,%3};"
                        : "+f"(c[mt][nt][0]), "+f"(c[mt][nt][1]),
                          "+f"(c[mt][nt][2]), "+f"(c[mt][nt][3])
                        : "r"(a[mt][0]), "r"(a[mt][1]), "r"(a[mt][2]), "r"(a[mt][3]),
                          "r"(b[nt][0]), "r"(b[nt][1]));
        }
        if (kb < 7) {
            store_stage(st ^ 1);
            __syncthreads();
        }
    }

    // epilogue: bias, fp32/fp16 stores, fused sdst (quad-reduce + atomicAdd)
    float bl[4][2], p2[4][2];
#pragma unroll
    for (int nt = 0; nt < 4; ++nt) {
        int col = col0 + wn * 32 + nt * 8 + (lane & 3) * 2;
        bl[nt][0] = __ldg(&bias[col + 0]);
        bl[nt][1] = __ldg(&bias[col + 1]);
        p2[nt][0] = __ldg(&phi[F + col + 0]);
        p2[nt][1] = __ldg(&phi[F + col + 1]);
    }
#pragma unroll
    for (int mt = 0; mt < 2; ++mt)
#pragma unroll
        for (int h = 0; h < 2; ++h) {
            int row = row0 + wm * 32 + mt * 16 + (lane >> 2) + h * 8;
            float sloc = 0.f;
#pragma unroll
            for (int nt = 0; nt < 4; ++nt) {
                int col = col0 + wn * 32 + nt * 8 + (lane & 3) * 2;
                float vx = c[mt][nt][h * 2 + 0] + bl[nt][0];
                float vy = c[mt][nt][h * 2 + 1] + bl[nt][1];
                *reinterpret_cast<float2*>(C + (size_t)row * F + col) = make_float2(vx, vy);
                *reinterpret_cast<__half2*>(Ch + (size_t)row * F + col) = __floats2half2_rn(vx, vy);
                sloc += vx * p2[nt][0] + vy * p2[nt][1];
            }
            sloc += __shfl_xor_sync(0xFFFFFFFFu, sloc, 1);
            sloc += __shfl_xor_sync(0xFFFFFFFFu, sloc, 2);
            if ((lane & 3) == 0) atomicAdd(&sdst[row], sloc);
        }
}

// ---------------- Kernel 2: fused scan+gather aggregate -------------------
// 2 warps per row. Phase A: front-batched (8-deep) adj stream read as uint4
// (adj is exactly 0.0f/1.0f so bit-tests are exact); one "any" ballot per
// chunk; single-nonzero fast path (71% of non-empty chunks); general
// ballot/popc compaction otherwise. Phase B: batch-4 gathers, expf inline.
constexpr int MAXI = 64;   // per half-row (mean ~20.5)

__device__ __forceinline__ void acc_half8(float acc[8], float e, uint4 h) {
    float2 f0 = __half22float2(*reinterpret_cast<__half2*>(&h.x));
    float2 f1 = __half22float2(*reinterpret_cast<__half2*>(&h.y));
    float2 f2 = __half22float2(*reinterpret_cast<__half2*>(&h.z));
    float2 f3 = __half22float2(*reinterpret_cast<__half2*>(&h.w));
    acc[0] += e * f0.x; acc[1] += e * f0.y;
    acc[2] += e * f1.x; acc[3] += e * f1.y;
    acc[4] += e * f2.x; acc[5] += e * f2.y;
    acc[6] += e * f3.x; acc[7] += e * f3.y;
}

__global__ void __launch_bounds__(256)
gat_aggregate_kernel(const float* __restrict__ adj,
                     const float* __restrict__ H,     // fp32 (self term)
                     const __half* __restrict__ Hh,   // fp16 (gather)
                     const float* __restrict__ sdst,
                     float* __restrict__ out)
{
    __shared__ int    s_idx[8][MAXI];
    __shared__ float4 s_part[4][64];
    __shared__ float  s_z[4];

    const int lane = threadIdx.x & 31;
    const int wid  = threadIdx.x >> 5;
    const int rloc = wid >> 1;
    const int half = wid & 1;
    const int row  = blockIdx.x * 4 + rloc;

    const uint4* arow = reinterpret_cast<const uint4*>(adj + (size_t)row * N)
                        + half * 1024;    // 4096 cols per half
    const int colbase = half * 4096;
    const unsigned lmask = (1u << lane) - 1;
    const unsigned FULL = 0xFFFFFFFFu;

    // ---- phase A: front-batched stream + tiered compaction ----
    int cnt = 0;
#pragma unroll 1
    for (int it0 = 0; it0 < 32; it0 += 8) {
        uint4 v[8];
#pragma unroll
        for (int u = 0; u < 8; ++u)              // 8 independent loads in flight
            v[u] = arow[(it0 + u) * 32 + lane];
#pragma unroll
        for (int u = 0; u < 8; ++u) {
            unsigned orv = v[u].x | v[u].y | v[u].z | v[u].w;
            unsigned bnz = __ballot_sync(FULL, orv != 0u);
            if (bnz == 0u) continue;             // ~53%: empty chunk

            const int chunkbase = colbase + (it0 + u) * 128;
            unsigned m4 = (v[u].x ? 1u : 0u) | (v[u].y ? 2u : 0u)
                        | (v[u].z ? 4u : 0u) | (v[u].w ? 8u : 0u);

            if (__popc(bnz) == 1) {              // one lane has data
                int src = __ffs(bnz) - 1;
                unsigned m4s = __shfl_sync(FULL, m4, src);
                if ((m4s & (m4s - 1)) == 0u) {   // exactly one nonzero: fast path
                    int col = chunkbase + src * 4 + (__ffs(m4s) - 1);
                    if (col != row) {
                        if (lane == 0 && cnt < MAXI) s_idx[wid][cnt] = col;
                        ++cnt;                   // uniform
                    }
                    continue;
                }
            }
            // general path
            int jb = chunkbase + lane * 4;
#pragma unroll
            for (int c = 0; c < 4; ++c) {
                unsigned m = __ballot_sync(FULL,
                    ((m4 >> c) & 1u) && (jb + c) != row);
                int pos = cnt + __popc(m & lmask);
                if (((m >> lane) & 1u) && pos < MAXI) s_idx[wid][pos] = jb + c;
                cnt += __popc(m);
            }
        }
    }
    if (cnt > MAXI) cnt = MAXI;
    __syncwarp();

    // ---- phase B: batch-4 gathers ----
    float Z = 0.f;
    float acc[8] = {0.f, 0.f, 0.f, 0.f, 0.f, 0.f, 0.f, 0.f};
    const uint4* hbase = reinterpret_cast<const uint4*>(Hh);
    int i = 0;
    for (; i + 4 <= cnt; i += 4) {
        int j0 = s_idx[wid][i + 0], j1 = s_idx[wid][i + 1];
        int j2 = s_idx[wid][i + 2], j3 = s_idx[wid][i + 3];
        float e0 = expf(__ldg(&sdst[j0])), e1 = expf(__ldg(&sdst[j1]));
        float e2 = expf(__ldg(&sdst[j2])), e3 = expf(__ldg(&sdst[j3]));
        uint4 h0 = __ldg(hbase + (size_t)j0 * 32 + lane);
        uint4 h1 = __ldg(hbase + (size_t)j1 * 32 + lane);
        uint4 h2 = __ldg(hbase + (size_t)j2 * 32 + lane);
        uint4 h3 = __ldg(hbase + (size_t)j3 * 32 + lane);
        Z += e0 + e1 + e2 + e3;
        acc_half8(acc, e0, h0);
        acc_half8(acc, e1, h1);
        acc_half8(acc, e2, h2);
        acc_half8(acc, e3, h3);
    }
    for (; i < cnt; ++i) {
        int j = s_idx[wid][i];
        float e = expf(__ldg(&sdst[j]));
        uint4 h = __ldg(hbase + (size_t)j * 32 + lane);
        Z += e;
        acc_half8(acc, e, h);
    }

    // ---- merge halves, self-loop, normalize, lrelu ----
    if (half == 1) {
        s_part[rloc][lane * 2]     = make_float4(acc[0], acc[1], acc[2], acc[3]);
        s_part[rloc][lane * 2 + 1] = make_float4(acc[4], acc[5], acc[6], acc[7]);
        if (lane == 0) s_z[rloc] = Z;
    }
    __syncthreads();

    if (half == 0) {
        float4 p0 = s_part[rloc][lane * 2];
        float4 p1 = s_part[rloc][lane * 2 + 1];
        acc[0] += p0.x; acc[1] += p0.y; acc[2] += p0.z; acc[3] += p0.w;
        acc[4] += p1.x; acc[5] += p1.y; acc[6] += p1.z; acc[7] += p1.w;
        Z += s_z[rloc];

        float e0 = expf(__ldg(&sdst[row]));      // self-loop, fp32, exactly once
        Z += e0;
        const float4* hs = reinterpret_cast<const float4*>(H + (size_t)row * F) + lane * 2;
        float4 hp = hs[0], hq = hs[1];
        acc[0] += e0 * hp.x; acc[1] += e0 * hp.y;
        acc[2] += e0 * hp.z; acc[3] += e0 * hp.w;
        acc[4] += e0 * hq.x; acc[5] += e0 * hq.y;
        acc[6] += e0 * hq.z; acc[7] += e0 * hq.w;

        const float inv = 1.0f / Z;
        float o[8];
#pragma unroll
        for (int k = 0; k < 8; ++k) {
            float v = acc[k] * inv;
            o[k] = v > 0.f ? v : 0.01f * v;
        }
        float4* orow = reinterpret_cast<float4*>(out + (size_t)row * F) + lane * 2;
        orow[0] = make_float4(o[0], o[1], o[2], o[3]);
        orow[1] = make_float4(o[4], o[5], o[6], o[7]);
    }
}

// ---------------- launch ----------------
extern "C" void kernel_launch(void* const* d_in, const int* in_sizes, int n_in,
                              void* d_out, int out_size)
{
    const float* adj    = (const float*)d_in[0];
    const float* x      = (const float*)d_in[1];
    const float* weight = (const float*)d_in[2];
    const float* bias   = (const float*)d_in[3];
    const float* phi    = (const float*)d_in[4];
    float* out = (float*)d_out;

    float*  H    = nullptr;
    __half* Hh   = nullptr;
    float*  sdst = nullptr;
    cudaGetSymbolAddress((void**)&H,    g_H);
    cudaGetSymbolAddress((void**)&Hh,   g_Hh);
    cudaGetSymbolAddress((void**)&sdst, g_sdst);

    cudaMemsetAsync(sdst, 0, N * sizeof(float));

    gemm_mma_kernel<<<dim3(F / 64, N / 128), 256>>>(x, weight, bias, phi, H, Hh, sdst);
    gat_aggregate_kernel<<<N / 4, 256>>>(adj, H, Hh, sdst, out);
}

// round 16
// speedup vs baseline: 1.0289x; 1.0289x over previous
#include <cuda_runtime.h>
#include <cuda_fp16.h>
#include <cstdint>

constexpr int N = 8192;
constexpr int F = 256;

// ---------------- scratch ----------------
__device__ __align__(16) float  g_H [(size_t)N * F];
__device__ __align__(16) __half g_Hh[(size_t)N * F];
__device__ __align__(16) float  g_sdst4[(size_t)N * 4];  // 4 col-block partials

__device__ __forceinline__ uint32_t tf32r(float x) {
    uint32_t u; asm("cvt.rna.tf32.f32 %0, %1;" : "=r"(u) : "f"(x));
    return u;
}

// ---------------- Kernel 1: H = x@W + bias (tf32 mma, 2-stage) + sdst slots -
__global__ void __launch_bounds__(256, 2)
gemm_mma_kernel(const float* __restrict__ A, const float* __restrict__ B,
                const float* __restrict__ bias, const float* __restrict__ phi,
                float* __restrict__ C, __half* __restrict__ Ch,
                float* __restrict__ sdst4)
{
    __shared__ uint32_t As[2][4][128][8];
    __shared__ uint32_t Bs[2][4][64][8];
    __shared__ float s_red[128];

    const int tid = threadIdx.x;
    const int lane = tid & 31, wid = tid >> 5;
    const int wm = wid & 3, wn = wid >> 2;
    const int row0 = blockIdx.y * 128, col0 = blockIdx.x * 64;

    float c[2][4][4];
#pragma unroll
    for (int mt = 0; mt < 2; ++mt)
#pragma unroll
        for (int nt = 0; nt < 4; ++nt)
#pragma unroll
            for (int e = 0; e < 4; ++e) c[mt][nt][e] = 0.f;

    int a_m[4], a_ks[4], a_q[4];
    const float* a_src[4];
#pragma unroll
    for (int i = 0; i < 4; ++i) {
        int idx = tid + i * 256;
        a_m[i] = idx >> 3; a_ks[i] = (idx >> 1) & 3; a_q[i] = idx & 1;
        a_src[i] = A + (size_t)(row0 + a_m[i]) * F + a_ks[i] * 8 + a_q[i] * 4;
    }
    int b_k[2], b_nb[2];
    const float* b_src[2];
#pragma unroll
    for (int i = 0; i < 2; ++i) {
        int idx = tid + i * 256;
        b_k[i] = idx >> 4; b_nb[i] = (idx & 15) * 4;
        b_src[i] = B + (size_t)b_k[i] * F + col0 + b_nb[i];
    }

    float4 ra[4], rb[2];
#pragma unroll
    for (int i = 0; i < 4; ++i) ra[i] = *reinterpret_cast<const float4*>(a_src[i]);
#pragma unroll
    for (int i = 0; i < 2; ++i) rb[i] = *reinterpret_cast<const float4*>(b_src[i]);

    auto store_stage = [&](int st) {
#pragma unroll
        for (int i = 0; i < 4; ++i) {
            uint32_t t[4] = {tf32r(ra[i].x), tf32r(ra[i].y), tf32r(ra[i].z), tf32r(ra[i].w)};
            int s = a_m[i] & 7;
            int qd = a_q[i] ^ (s >> 2), p = s & 3;
            uint32_t* dst = &As[st][a_ks[i]][a_m[i]][qd * 4];
            dst[0] = t[0 ^ p]; dst[1] = t[1 ^ p];
            dst[2] = t[2 ^ p]; dst[3] = t[3 ^ p];
        }
#pragma unroll
        for (int i = 0; i < 2; ++i) {
            uint32_t t[4] = {tf32r(rb[i].x), tf32r(rb[i].y), tf32r(rb[i].z), tf32r(rb[i].w)};
#pragma unroll
            for (int e = 0; e < 4; ++e) {
                int n = b_nb[i] + e;
                Bs[st][b_k[i] >> 3][n][(b_k[i] & 7) ^ (n & 7)] = t[e];
            }
        }
    };

    store_stage(0);
    __syncthreads();

#pragma unroll
    for (int kb = 0; kb < 8; ++kb) {
        const int st = kb & 1;
        if (kb < 7) {
#pragma unroll
            for (int i = 0; i < 4; ++i)
                ra[i] = *reinterpret_cast<const float4*>(a_src[i] + (kb + 1) * 32);
#pragma unroll
            for (int i = 0; i < 2; ++i)
                rb[i] = *reinterpret_cast<const float4*>(b_src[i] + (size_t)(kb + 1) * 32 * F);
        }
#pragma unroll
        for (int ks = 0; ks < 4; ++ks) {
            uint32_t a[2][4], b[4][2];
#pragma unroll
            for (int mt = 0; mt < 2; ++mt) {
                int r = wm * 32 + mt * 16 + (lane >> 2);
                int j0 = (lane & 3) ^ (r & 7);
                a[mt][0] = As[st][ks][r][j0];
                a[mt][1] = As[st][ks][r + 8][j0];
                a[mt][2] = As[st][ks][r][j0 ^ 4];
                a[mt][3] = As[st][ks][r + 8][j0 ^ 4];
            }
#pragma unroll
            for (int nt = 0; nt < 4; ++nt) {
                int n = wn * 32 + nt * 8 + (lane >> 2);
                int j0 = (lane & 3) ^ (n & 7);
                b[nt][0] = Bs[st][ks][n][j0];
                b[nt][1] = Bs[st][ks][n][j0 ^ 4];
            }
#pragma unroll
            for (int mt = 0; mt < 2; ++mt)
#pragma unroll
                for (int nt = 0; nt < 4; ++nt)
                    asm volatile(
                        "mma.sync.aligned.m16n8k8.row.col.f32.tf32.tf32.f32 "
                        "{%0,%1,%2,%3}, {%4,%5,%6,%7}, {%8,%9}, {%0,%1,%2,%3};"
                        : "+f"(c[mt][nt][0]), "+f"(c[mt][nt][1]),
                          "+f"(c[mt][nt][2]), "+f"(c[mt][nt][3])
                        : "r"(a[mt][0]), "r"(a[mt][1]), "r"(a[mt][2]), "r"(a[mt][3]),
                          "r"(b[nt][0]), "r"(b[nt][1]));
        }
        if (kb < 7) {
            store_stage(st ^ 1);
            __syncthreads();
        }
    }

    // epilogue: bias, fp32/fp16 stores; per-(CTA,row) sdst partial via smem
    float bl[4][2], p2[4][2];
#pragma unroll
    for (int nt = 0; nt < 4; ++nt) {
        int col = col0 + wn * 32 + nt * 8 + (lane & 3) * 2;
        bl[nt][0] = __ldg(&bias[col + 0]);
        bl[nt][1] = __ldg(&bias[col + 1]);
        p2[nt][0] = __ldg(&phi[F + col + 0]);
        p2[nt][1] = __ldg(&phi[F + col + 1]);
    }
    float sl[2][2];
#pragma unroll
    for (int mt = 0; mt < 2; ++mt)
#pragma unroll
        for (int h = 0; h < 2; ++h) {
            int row = row0 + wm * 32 + mt * 16 + (lane >> 2) + h * 8;
            float sloc = 0.f;
#pragma unroll
            for (int nt = 0; nt < 4; ++nt) {
                int col = col0 + wn * 32 + nt * 8 + (lane & 3) * 2;
                float vx = c[mt][nt][h * 2 + 0] + bl[nt][0];
                float vy = c[mt][nt][h * 2 + 1] + bl[nt][1];
                *reinterpret_cast<float2*>(C + (size_t)row * F + col) = make_float2(vx, vy);
                *reinterpret_cast<__half2*>(Ch + (size_t)row * F + col) = __floats2half2_rn(vx, vy);
                sloc += vx * p2[nt][0] + vy * p2[nt][1];
            }
            sloc += __shfl_xor_sync(0xFFFFFFFFu, sloc, 1);
            sloc += __shfl_xor_sync(0xFFFFFFFFu, sloc, 2);
            sl[mt][h] = sloc;                    // all quad lanes hold the sum
        }

    if (wn == 1 && (lane & 3) == 0) {
#pragma unroll
        for (int mt = 0; mt < 2; ++mt)
#pragma unroll
            for (int h = 0; h < 2; ++h) {
                int ml = wm * 32 + mt * 16 + h * 8 + (lane >> 2);
                s_red[ml] = sl[mt][h];
            }
    }
    __syncthreads();
    if (wn == 0 && (lane & 3) == 0) {
#pragma unroll
        for (int mt = 0; mt < 2; ++mt)
#pragma unroll
            for (int h = 0; h < 2; ++h) {
                int ml = wm * 32 + mt * 16 + h * 8 + (lane >> 2);
                sdst4[(size_t)(row0 + ml) * 4 + blockIdx.x] = sl[mt][h] + s_red[ml];
            }
    }
}

// ---------------- Kernel 2: fused scan+gather aggregate (R15 structure) -----
constexpr int MAXI = 64;   // per half-row (mean ~20.5)

__device__ __forceinline__ void acc_half8(float acc[8], float e, uint4 h) {
    float2 f0 = __half22float2(*reinterpret_cast<__half2*>(&h.x));
    float2 f1 = __half22float2(*reinterpret_cast<__half2*>(&h.y));
    float2 f2 = __half22float2(*reinterpret_cast<__half2*>(&h.z));
    float2 f3 = __half22float2(*reinterpret_cast<__half2*>(&h.w));
    acc[0] += e * f0.x; acc[1] += e * f0.y;
    acc[2] += e * f1.x; acc[3] += e * f1.y;
    acc[4] += e * f2.x; acc[5] += e * f2.y;
    acc[6] += e * f3.x; acc[7] += e * f3.y;
}

__device__ __forceinline__ float eshift(const float4& s) {
    return expf(s.x + s.y + s.z + s.w);
}

__global__ void __launch_bounds__(256)
gat_aggregate_kernel(const float* __restrict__ adj,
                     const float* __restrict__ H,     // fp32 (self term)
                     const __half* __restrict__ Hh,   // fp16 (gather)
                     const float4* __restrict__ sd4,  // sdst partial slots
                     float* __restrict__ out)
{
    __shared__ int    s_idx[8][MAXI];
    __shared__ float4 s_part[4][64];
    __shared__ float  s_z[4];

    const int lane = threadIdx.x & 31;
    const int wid  = threadIdx.x >> 5;
    const int rloc = wid >> 1;
    const int half = wid & 1;
    const int row  = blockIdx.x * 4 + rloc;

    const uint4* arow = reinterpret_cast<const uint4*>(adj + (size_t)row * N)
                        + half * 1024;
    const int colbase = half * 4096;
    const unsigned lmask = (1u << lane) - 1;
    const unsigned FULL = 0xFFFFFFFFu;

    // ---- phase A: front-batched stream + tiered compaction ----
    int cnt = 0;
#pragma unroll 1
    for (int it0 = 0; it0 < 32; it0 += 8) {
        uint4 v[8];
#pragma unroll
        for (int u = 0; u < 8; ++u)
            v[u] = arow[(it0 + u) * 32 + lane];
#pragma unroll
        for (int u = 0; u < 8; ++u) {
            unsigned orv = v[u].x | v[u].y | v[u].z | v[u].w;
            unsigned bnz = __ballot_sync(FULL, orv != 0u);
            if (bnz == 0u) continue;

            const int chunkbase = colbase + (it0 + u) * 128;
            unsigned m4 = (v[u].x ? 1u : 0u) | (v[u].y ? 2u : 0u)
                        | (v[u].z ? 4u : 0u) | (v[u].w ? 8u : 0u);

            if (__popc(bnz) == 1) {
                int src = __ffs(bnz) - 1;
                unsigned m4s = __shfl_sync(FULL, m4, src);
                if ((m4s & (m4s - 1)) == 0u) {
                    int col = chunkbase + src * 4 + (__ffs(m4s) - 1);
                    if (col != row) {
                        if (lane == 0 && cnt < MAXI) s_idx[wid][cnt] = col;
                        ++cnt;
                    }
                    continue;
                }
            }
            int jb = chunkbase + lane * 4;
#pragma unroll
            for (int c = 0; c < 4; ++c) {
                unsigned m = __ballot_sync(FULL,
                    ((m4 >> c) & 1u) && (jb + c) != row);
                int pos = cnt + __popc(m & lmask);
                if (((m >> lane) & 1u) && pos < MAXI) s_idx[wid][pos] = jb + c;
                cnt += __popc(m);
            }
        }
    }
    if (cnt > MAXI) cnt = MAXI;
    __syncwarp();

    // ---- phase B: batch-4 gathers; e = expf(sum of 4 sdst slots) ----
    float Z = 0.f;
    float acc[8] = {0.f, 0.f, 0.f, 0.f, 0.f, 0.f, 0.f, 0.f};
    const uint4* hbase = reinterpret_cast<const uint4*>(Hh);
    int i = 0;
    for (; i + 4 <= cnt; i += 4) {
        int j0 = s_idx[wid][i + 0], j1 = s_idx[wid][i + 1];
        int j2 = s_idx[wid][i + 2], j3 = s_idx[wid][i + 3];
        float4 s0 = __ldg(sd4 + j0), s1 = __ldg(sd4 + j1);
        float4 s2 = __ldg(sd4 + j2), s3 = __ldg(sd4 + j3);
        uint4 h0 = __ldg(hbase + (size_t)j0 * 32 + lane);
        uint4 h1 = __ldg(hbase + (size_t)j1 * 32 + lane);
        uint4 h2 = __ldg(hbase + (size_t)j2 * 32 + lane);
        uint4 h3 = __ldg(hbase + (size_t)j3 * 32 + lane);
        float e0 = eshift(s0), e1 = eshift(s1), e2 = eshift(s2), e3 = eshift(s3);
        Z += e0 + e1 + e2 + e3;
        acc_half8(acc, e0, h0);
        acc_half8(acc, e1, h1);
        acc_half8(acc, e2, h2);
        acc_half8(acc, e3, h3);
    }
    for (; i < cnt; ++i) {
        int j = s_idx[wid][i];
        float e = eshift(__ldg(sd4 + j));
        uint4 h = __ldg(hbase + (size_t)j * 32 + lane);
        Z += e;
        acc_half8(acc, e, h);
    }

    // ---- merge halves, self-loop, normalize, lrelu ----
    if (half == 1) {
        s_part[rloc][lane * 2]     = make_float4(acc[0], acc[1], acc[2], acc[3]);
        s_part[rloc][lane * 2 + 1] = make_float4(acc[4], acc[5], acc[6], acc[7]);
        if (lane == 0) s_z[rloc] = Z;
    }
    __syncthreads();

    if (half == 0) {
        float4 p0 = s_part[rloc][lane * 2];
        float4 p1 = s_part[rloc][lane * 2 + 1];
        acc[0] += p0.x; acc[1] += p0.y; acc[2] += p0.z; acc[3] += p0.w;
        acc[4] += p1.x; acc[5] += p1.y; acc[6] += p1.z; acc[7] += p1.w;
        Z += s_z[rloc];

        float e0 = eshift(__ldg(sd4 + row));     // self-loop, exactly once
        Z += e0;
        const float4* hs = reinterpret_cast<const float4*>(H + (size_t)row * F) + lane * 2;
        float4 hp = hs[0], hq = hs[1];
        acc[0] += e0 * hp.x; acc[1] += e0 * hp.y;
        acc[2] += e0 * hp.z; acc[3] += e0 * hp.w;
        acc[4] += e0 * hq.x; acc[5] += e0 * hq.y;
        acc[6] += e0 * hq.z; acc[7] += e0 * hq.w;

        const float inv = 1.0f / Z;
        float o[8];
#pragma unroll
        for (int k = 0; k < 8; ++k) {
            float v = acc[k] * inv;
            o[k] = v > 0.f ? v : 0.01f * v;
        }
        float4* orow = reinterpret_cast<float4*>(out + (size_t)row * F) + lane * 2;
        orow[0] = make_float4(o[0], o[1], o[2], o[3]);
        orow[1] = make_float4(o[4], o[5], o[6], o[7]);
    }
}

// ---------------- launch ----------------
extern "C" void kernel_launch(void* const* d_in, const int* in_sizes, int n_in,
                              void* d_out, int out_size)
{
    const float* adj    = (const float*)d_in[0];
    const float* x      = (const float*)d_in[1];
    const float* weight = (const float*)d_in[2];
    const float* bias   = (const float*)d_in[3];
    const float* phi    = (const float*)d_in[4];
    float* out = (float*)d_out;

    float*  H     = nullptr;
    __half* Hh    = nullptr;
    float*  sdst4 = nullptr;
    cudaGetSymbolAddress((void**)&H,     g_H);
    cudaGetSymbolAddress((void**)&Hh,    g_Hh);
    cudaGetSymbolAddress((void**)&sdst4, g_sdst4);

    gemm_mma_kernel<<<dim3(F / 64, N / 128), 256>>>(x, weight, bias, phi, H, Hh, sdst4);
    gat_aggregate_kernel<<<N / 4, 256>>>(adj, H, Hh,
                                         reinterpret_cast<const float4*>(sdst4), out);
}

// round 17
// speedup vs baseline: 1.1641x; 1.1314x over previous
#include <cuda_runtime.h>
#include <cuda_fp16.h>
#include <cstdint>

constexpr int N = 8192;
constexpr int F = 256;

// ---------------- scratch ----------------
__device__ __align__(16) float  g_H [(size_t)N * F];
__device__ __align__(16) __half g_Hh[(size_t)N * F];
__device__ __align__(16) float  g_sdst4[(size_t)N * 4];  // 4 col-block partials

__device__ __forceinline__ uint32_t tf32r(float x) {
    uint32_t u; asm("cvt.rna.tf32.f32 %0, %1;" : "=r"(u) : "f"(x));
    return u;
}
// PDL primitives (sm_90+ baseline PTX, no arch suffix needed)
__device__ __forceinline__ void pdl_trigger() {
    asm volatile("griddepcontrol.launch_dependents;");
}
__device__ __forceinline__ void pdl_wait() {
    asm volatile("griddepcontrol.wait;" ::: "memory");
}

// ---------------- Kernel 1: H = x@W + bias (tf32 mma, 2-stage) + sdst slots -
__global__ void __launch_bounds__(256, 2)
gemm_mma_kernel(const float* __restrict__ A, const float* __restrict__ B,
                const float* __restrict__ bias, const float* __restrict__ phi,
                float* __restrict__ C, __half* __restrict__ Ch,
                float* __restrict__ sdst4)
{
    // let the dependent (aggregate) start streaming adj immediately
    pdl_trigger();

    __shared__ uint32_t As[2][4][128][8];
    __shared__ uint32_t Bs[2][4][64][8];
    __shared__ float s_red[128];

    const int tid = threadIdx.x;
    const int lane = tid & 31, wid = tid >> 5;
    const int wm = wid & 3, wn = wid >> 2;
    const int row0 = blockIdx.y * 128, col0 = blockIdx.x * 64;

    float c[2][4][4];
#pragma unroll
    for (int mt = 0; mt < 2; ++mt)
#pragma unroll
        for (int nt = 0; nt < 4; ++nt)
#pragma unroll
            for (int e = 0; e < 4; ++e) c[mt][nt][e] = 0.f;

    int a_m[4], a_ks[4], a_q[4];
    const float* a_src[4];
#pragma unroll
    for (int i = 0; i < 4; ++i) {
        int idx = tid + i * 256;
        a_m[i] = idx >> 3; a_ks[i] = (idx >> 1) & 3; a_q[i] = idx & 1;
        a_src[i] = A + (size_t)(row0 + a_m[i]) * F + a_ks[i] * 8 + a_q[i] * 4;
    }
    int b_k[2], b_nb[2];
    const float* b_src[2];
#pragma unroll
    for (int i = 0; i < 2; ++i) {
        int idx = tid + i * 256;
        b_k[i] = idx >> 4; b_nb[i] = (idx & 15) * 4;
        b_src[i] = B + (size_t)b_k[i] * F + col0 + b_nb[i];
    }

    float4 ra[4], rb[2];
#pragma unroll
    for (int i = 0; i < 4; ++i) ra[i] = *reinterpret_cast<const float4*>(a_src[i]);
#pragma unroll
    for (int i = 0; i < 2; ++i) rb[i] = *reinterpret_cast<const float4*>(b_src[i]);

    auto store_stage = [&](int st) {
#pragma unroll
        for (int i = 0; i < 4; ++i) {
            uint32_t t[4] = {tf32r(ra[i].x), tf32r(ra[i].y), tf32r(ra[i].z), tf32r(ra[i].w)};
            int s = a_m[i] & 7;
            int qd = a_q[i] ^ (s >> 2), p = s & 3;
            uint32_t* dst = &As[st][a_ks[i]][a_m[i]][qd * 4];
            dst[0] = t[0 ^ p]; dst[1] = t[1 ^ p];
            dst[2] = t[2 ^ p]; dst[3] = t[3 ^ p];
        }
#pragma unroll
        for (int i = 0; i < 2; ++i) {
            uint32_t t[4] = {tf32r(rb[i].x), tf32r(rb[i].y), tf32r(rb[i].z), tf32r(rb[i].w)};
#pragma unroll
            for (int e = 0; e < 4; ++e) {
                int n = b_nb[i] + e;
                Bs[st][b_k[i] >> 3][n][(b_k[i] & 7) ^ (n & 7)] = t[e];
            }
        }
    };

    store_stage(0);
    __syncthreads();

#pragma unroll
    for (int kb = 0; kb < 8; ++kb) {
        const int st = kb & 1;
        if (kb < 7) {
#pragma unroll
            for (int i = 0; i < 4; ++i)
                ra[i] = *reinterpret_cast<const float4*>(a_src[i] + (kb + 1) * 32);
#pragma unroll
            for (int i = 0; i < 2; ++i)
                rb[i] = *reinterpret_cast<const float4*>(b_src[i] + (size_t)(kb + 1) * 32 * F);
        }
#pragma unroll
        for (int ks = 0; ks < 4; ++ks) {
            uint32_t a[2][4], b[4][2];
#pragma unroll
            for (int mt = 0; mt < 2; ++mt) {
                int r = wm * 32 + mt * 16 + (lane >> 2);
                int j0 = (lane & 3) ^ (r & 7);
                a[mt][0] = As[st][ks][r][j0];
                a[mt][1] = As[st][ks][r + 8][j0];
                a[mt][2] = As[st][ks][r][j0 ^ 4];
                a[mt][3] = As[st][ks][r + 8][j0 ^ 4];
            }
#pragma unroll
            for (int nt = 0; nt < 4; ++nt) {
                int n = wn * 32 + nt * 8 + (lane >> 2);
                int j0 = (lane & 3) ^ (n & 7);
                b[nt][0] = Bs[st][ks][n][j0];
                b[nt][1] = Bs[st][ks][n][j0 ^ 4];
            }
#pragma unroll
            for (int mt = 0; mt < 2; ++mt)
#pragma unroll
                for (int nt = 0; nt < 4; ++nt)
                    asm volatile(
                        "mma.sync.aligned.m16n8k8.row.col.f32.tf32.tf32.f32 "
                        "{%0,%1,%2,%3}, {%4,%5,%6,%7}, {%8,%9}, {%0,%1,%2,%3};"
                        : "+f"(c[mt][nt][0]), "+f"(c[mt][nt][1]),
                          "+f"(c[mt][nt][2]), "+f"(c[mt][nt][3])
                        : "r"(a[mt][0]), "r"(a[mt][1]), "r"(a[mt][2]), "r"(a[mt][3]),
                          "r"(b[nt][0]), "r"(b[nt][1]));
        }
        if (kb < 7) {
            store_stage(st ^ 1);
            __syncthreads();
        }
    }

    // epilogue: bias, fp32/fp16 stores; per-(CTA,row) sdst partial via smem
    float bl[4][2], p2[4][2];
#pragma unroll
    for (int nt = 0; nt < 4; ++nt) {
        int col = col0 + wn * 32 + nt * 8 + (lane & 3) * 2;
        bl[nt][0] = __ldg(&bias[col + 0]);
        bl[nt][1] = __ldg(&bias[col + 1]);
        p2[nt][0] = __ldg(&phi[F + col + 0]);
        p2[nt][1] = __ldg(&phi[F + col + 1]);
    }
    float sl[2][2];
#pragma unroll
    for (int mt = 0; mt < 2; ++mt)
#pragma unroll
        for (int h = 0; h < 2; ++h) {
            int row = row0 + wm * 32 + mt * 16 + (lane >> 2) + h * 8;
            float sloc = 0.f;
#pragma unroll
            for (int nt = 0; nt < 4; ++nt) {
                int col = col0 + wn * 32 + nt * 8 + (lane & 3) * 2;
                float vx = c[mt][nt][h * 2 + 0] + bl[nt][0];
                float vy = c[mt][nt][h * 2 + 1] + bl[nt][1];
                *reinterpret_cast<float2*>(C + (size_t)row * F + col) = make_float2(vx, vy);
                *reinterpret_cast<__half2*>(Ch + (size_t)row * F + col) = __floats2half2_rn(vx, vy);
                sloc += vx * p2[nt][0] + vy * p2[nt][1];
            }
            sloc += __shfl_xor_sync(0xFFFFFFFFu, sloc, 1);
            sloc += __shfl_xor_sync(0xFFFFFFFFu, sloc, 2);
            sl[mt][h] = sloc;
        }

    if (wn == 1 && (lane & 3) == 0) {
#pragma unroll
        for (int mt = 0; mt < 2; ++mt)
#pragma unroll
            for (int h = 0; h < 2; ++h) {
                int ml = wm * 32 + mt * 16 + h * 8 + (lane >> 2);
                s_red[ml] = sl[mt][h];
            }
    }
    __syncthreads();
    if (wn == 0 && (lane & 3) == 0) {
#pragma unroll
        for (int mt = 0; mt < 2; ++mt)
#pragma unroll
            for (int h = 0; h < 2; ++h) {
                int ml = wm * 32 + mt * 16 + h * 8 + (lane >> 2);
                sdst4[(size_t)(row0 + ml) * 4 + blockIdx.x] = sl[mt][h] + s_red[ml];
            }
    }
}

// ---------------- Kernel 2: aggregate; phase A overlaps GEMM via PDL --------
constexpr int MAXI = 64;   // per half-row (mean ~20.5)

__device__ __forceinline__ void acc_half8(float acc[8], float e, uint4 h) {
    float2 f0 = __half22float2(*reinterpret_cast<__half2*>(&h.x));
    float2 f1 = __half22float2(*reinterpret_cast<__half2*>(&h.y));
    float2 f2 = __half22float2(*reinterpret_cast<__half2*>(&h.z));
    float2 f3 = __half22float2(*reinterpret_cast<__half2*>(&h.w));
    acc[0] += e * f0.x; acc[1] += e * f0.y;
    acc[2] += e * f1.x; acc[3] += e * f1.y;
    acc[4] += e * f2.x; acc[5] += e * f2.y;
    acc[6] += e * f3.x; acc[7] += e * f3.y;
}

__device__ __forceinline__ float eshift(const float4& s) {
    return expf(s.x + s.y + s.z + s.w);
}

__global__ void __launch_bounds__(256)
gat_aggregate_kernel(const float* __restrict__ adj,
                     const float* __restrict__ H,
                     const __half* __restrict__ Hh,
                     const float4* __restrict__ sd4,
                     float* __restrict__ out)
{
    __shared__ int    s_idx[8][MAXI];
    __shared__ float4 s_part[4][64];
    __shared__ float  s_z[4];

    const int lane = threadIdx.x & 31;
    const int wid  = threadIdx.x >> 5;
    const int rloc = wid >> 1;
    const int half = wid & 1;
    const int row  = blockIdx.x * 4 + rloc;

    const uint4* arow = reinterpret_cast<const uint4*>(adj + (size_t)row * N)
                        + half * 1024;
    const int colbase = half * 4096;
    const unsigned lmask = (1u << lane) - 1;
    const unsigned FULL = 0xFFFFFFFFu;

    // ---- phase A: adj stream + compaction (independent of GEMM outputs) ----
    int cnt = 0;
#pragma unroll 1
    for (int it0 = 0; it0 < 32; it0 += 8) {
        uint4 v[8];
#pragma unroll
        for (int u = 0; u < 8; ++u)
            v[u] = arow[(it0 + u) * 32 + lane];
#pragma unroll
        for (int u = 0; u < 8; ++u) {
            unsigned orv = v[u].x | v[u].y | v[u].z | v[u].w;
            unsigned bnz = __ballot_sync(FULL, orv != 0u);
            if (bnz == 0u) continue;

            const int chunkbase = colbase + (it0 + u) * 128;
            unsigned m4 = (v[u].x ? 1u : 0u) | (v[u].y ? 2u : 0u)
                        | (v[u].z ? 4u : 0u) | (v[u].w ? 8u : 0u);

            if (__popc(bnz) == 1) {
                int src = __ffs(bnz) - 1;
                unsigned m4s = __shfl_sync(FULL, m4, src);
                if ((m4s & (m4s - 1)) == 0u) {
                    int col = chunkbase + src * 4 + (__ffs(m4s) - 1);
                    if (col != row) {
                        if (lane == 0 && cnt < MAXI) s_idx[wid][cnt] = col;
                        ++cnt;
                    }
                    continue;
                }
            }
            int jb = chunkbase + lane * 4;
#pragma unroll
            for (int c = 0; c < 4; ++c) {
                unsigned m = __ballot_sync(FULL,
                    ((m4 >> c) & 1u) && (jb + c) != row);
                int pos = cnt + __popc(m & lmask);
                if (((m >> lane) & 1u) && pos < MAXI) s_idx[wid][pos] = jb + c;
                cnt += __popc(m);
            }
        }
    }
    if (cnt > MAXI) cnt = MAXI;
    __syncwarp();

    // ---- wait for GEMM's H / Hh / sdst4 before phase B ----
    pdl_wait();

    // ---- phase B: batch-4 gathers; e = expf(sum of 4 sdst slots) ----
    float Z = 0.f;
    float acc[8] = {0.f, 0.f, 0.f, 0.f, 0.f, 0.f, 0.f, 0.f};
    const uint4* hbase = reinterpret_cast<const uint4*>(Hh);
    int i = 0;
    for (; i + 4 <= cnt; i += 4) {
        int j0 = s_idx[wid][i + 0], j1 = s_idx[wid][i + 1];
        int j2 = s_idx[wid][i + 2], j3 = s_idx[wid][i + 3];
        float4 s0 = __ldg(sd4 + j0), s1 = __ldg(sd4 + j1);
        float4 s2 = __ldg(sd4 + j2), s3 = __ldg(sd4 + j3);
        uint4 h0 = __ldg(hbase + (size_t)j0 * 32 + lane);
        uint4 h1 = __ldg(hbase + (size_t)j1 * 32 + lane);
        uint4 h2 = __ldg(hbase + (size_t)j2 * 32 + lane);
        uint4 h3 = __ldg(hbase + (size_t)j3 * 32 + lane);
        float e0 = eshift(s0), e1 = eshift(s1), e2 = eshift(s2), e3 = eshift(s3);
        Z += e0 + e1 + e2 + e3;
        acc_half8(acc, e0, h0);
        acc_half8(acc, e1, h1);
        acc_half8(acc, e2, h2);
        acc_half8(acc, e3, h3);
    }
    for (; i < cnt; ++i) {
        int j = s_idx[wid][i];
        float e = eshift(__ldg(sd4 + j));
        uint4 h = __ldg(hbase + (size_t)j * 32 + lane);
        Z += e;
        acc_half8(acc, e, h);
    }

    // ---- merge halves, self-loop, normalize, lrelu ----
    if (half == 1) {
        s_part[rloc][lane * 2]     = make_float4(acc[0], acc[1], acc[2], acc[3]);
        s_part[rloc][lane * 2 + 1] = make_float4(acc[4], acc[5], acc[6], acc[7]);
        if (lane == 0) s_z[rloc] = Z;
    }
    __syncthreads();

    if (half == 0) {
        float4 p0 = s_part[rloc][lane * 2];
        float4 p1 = s_part[rloc][lane * 2 + 1];
        acc[0] += p0.x; acc[1] += p0.y; acc[2] += p0.z; acc[3] += p0.w;
        acc[4] += p1.x; acc[5] += p1.y; acc[6] += p1.z; acc[7] += p1.w;
        Z += s_z[rloc];

        float e0 = eshift(__ldg(sd4 + row));     // self-loop, exactly once
        Z += e0;
        const float4* hs = reinterpret_cast<const float4*>(H + (size_t)row * F) + lane * 2;
        float4 hp = hs[0], hq = hs[1];
        acc[0] += e0 * hp.x; acc[1] += e0 * hp.y;
        acc[2] += e0 * hp.z; acc[3] += e0 * hp.w;
        acc[4] += e0 * hq.x; acc[5] += e0 * hq.y;
        acc[6] += e0 * hq.z; acc[7] += e0 * hq.w;

        const float inv = 1.0f / Z;
        float o[8];
#pragma unroll
        for (int k = 0; k < 8; ++k) {
            float v = acc[k] * inv;
            o[k] = v > 0.f ? v : 0.01f * v;
        }
        float4* orow = reinterpret_cast<float4*>(out + (size_t)row * F) + lane * 2;
        orow[0] = make_float4(o[0], o[1], o[2], o[3]);
        orow[1] = make_float4(o[4], o[5], o[6], o[7]);
    }
}

// ---------------- launch: PDL pair on one stream ----------------------------
extern "C" void kernel_launch(void* const* d_in, const int* in_sizes, int n_in,
                              void* d_out, int out_size)
{
    const float* adj    = (const float*)d_in[0];
    const float* x      = (const float*)d_in[1];
    const float* weight = (const float*)d_in[2];
    const float* bias   = (const float*)d_in[3];
    const float* phi    = (const float*)d_in[4];
    float* out = (float*)d_out;

    float*  H     = nullptr;
    __half* Hh    = nullptr;
    float*  sdst4 = nullptr;
    cudaGetSymbolAddress((void**)&H,     g_H);
    cudaGetSymbolAddress((void**)&Hh,    g_Hh);
    cudaGetSymbolAddress((void**)&sdst4, g_sdst4);

    gemm_mma_kernel<<<dim3(F / 64, N / 128), 256>>>(x, weight, bias, phi, H, Hh, sdst4);

    // dependent launch: may start (phase A) while the GEMM is still running
    cudaLaunchConfig_t cfg = {};
    cfg.gridDim = dim3(N / 4);
    cfg.blockDim = dim3(256);
    cudaLaunchAttribute attrs[1];
    attrs[0].id = cudaLaunchAttributeProgrammaticStreamSerialization;
    attrs[0].val.programmaticStreamSerializationAllowed = 1;
    cfg.attrs = attrs;
    cfg.numAttrs = 1;
    cudaLaunchKernelEx(&cfg, gat_aggregate_kernel, adj, H, Hh,
                       (const float4*)sdst4, out);
}